// round 7
// baseline (speedup 1.0000x reference)
#include <cuda_runtime.h>
#include <cuda_fp16.h>
#include <math.h>
#include <stdint.h>

// ---------------- problem constants ----------------
#define B_   8
#define E_   8
#define C_   128
#define KW_  512
#define Mtot 16384          // B*L
#define KKd  4096           // KW*E
#define NNd  256            // 2*C

// ---------------- GEMM tiling ----------------
#define MT     64           // CTA M tile
#define KC     32           // K chunk (fp16 elems)
#define NCHUNK (KKd / KC)   // 128
#define NTH    256          // 8 warps: 2(M) x 4(N), warp tile 32x64
#define NCTA   (Mtot / MT)  // 256
#define STAGES 3

// smem (bytes)
#define PITCH   80          // 40 fp16 per row -> conflict-free ldmatrix
#define A_STG   (64 * PITCH)         // 5120 per stage
#define B_STG   (256 * PITCH)        // 20480 per stage
#define SM_A    0
#define SM_B    (STAGES * A_STG)     // 15360
#define SM_PIPE (SM_B + STAGES * B_STG)  // 76800
// epilogue v2 tile overlay: [64][132] floats = 33792 B (fits in pipe region)
#define VPITCH  132
#define SMEMSZ  SM_PIPE

// fp16 weights, [n][kk] K-major; n<128 -> W1, n>=128 -> W2
__device__ __half g_Bh[(size_t)NNd * KKd];

// ---------------- helpers ----------------
__device__ __forceinline__ uint32_t smem_u32(const void* p) {
    uint32_t a;
    asm("{ .reg .u64 t; cvta.to.shared.u64 t, %1; cvt.u32.u64 %0, t; }" : "=r"(a) : "l"(p));
    return a;
}
__device__ __forceinline__ uint32_t pack_h2(float x, float y) {
    __half2 t = __floats2half2_rn(x, y);
    return *reinterpret_cast<uint32_t*>(&t);
}
__device__ __forceinline__ void ldmx4(uint32_t* r, uint32_t addr) {
    asm volatile("ldmatrix.sync.aligned.m8n8.x4.shared.b16 {%0,%1,%2,%3}, [%4];"
                 : "=r"(r[0]), "=r"(r[1]), "=r"(r[2]), "=r"(r[3]) : "r"(addr));
}
__device__ __forceinline__ void mma16816(float* d, const uint32_t* a, uint32_t b0, uint32_t b1) {
    asm volatile("mma.sync.aligned.m16n8k16.row.col.f32.f16.f16.f32 "
                 "{%0,%1,%2,%3}, {%4,%5,%6,%7}, {%8,%9}, {%0,%1,%2,%3};"
                 : "+f"(d[0]), "+f"(d[1]), "+f"(d[2]), "+f"(d[3])
                 : "r"(a[0]), "r"(a[1]), "r"(a[2]), "r"(a[3]), "r"(b0), "r"(b1));
}
__device__ __forceinline__ void sts64(uint32_t a, uint32_t x, uint32_t y) {
    asm volatile("st.shared.v2.b32 [%0], {%1,%2};" :: "r"(a), "r"(x), "r"(y) : "memory");
}
__device__ __forceinline__ void stsf2(uint32_t a, float x, float y) {
    asm volatile("st.shared.v2.f32 [%0], {%1,%2};" :: "r"(a), "f"(x), "f"(y) : "memory");
}
__device__ __forceinline__ void cpasync16(uint32_t dst, const void* src) {
    asm volatile("cp.async.cg.shared.global [%0], [%1], 16;" :: "r"(dst), "l"(src) : "memory");
}
__device__ __forceinline__ void cp_commit() { asm volatile("cp.async.commit_group;" ::: "memory"); }
__device__ __forceinline__ void cp_wait1() { asm volatile("cp.async.wait_group 1;" ::: "memory"); }
__device__ __forceinline__ void cp_wait0() { asm volatile("cp.async.wait_group 0;" ::: "memory"); }
__device__ __forceinline__ void atomicMaxFloat(float* addr, float val) {
    if (val >= 0.0f) atomicMax((int*)addr, __float_as_int(val));
    else             atomicMin((unsigned int*)addr, __float_as_uint(val));
}

// ---------------- prep: weights -> fp16 [n][kk], coalesced; also init out ----------------
__global__ void prep_weights(const float* __restrict__ W1, const float* __restrict__ W2,
                             float* __restrict__ out) {
    int idx = blockIdx.x * blockDim.x + threadIdx.x;   // over C_*KW_ = 65536
    if (idx < B_ * C_) out[idx] = -INFINITY;
    if (idx >= C_ * KW_) return;
    int c = idx / KW_;
    int k = idx % KW_;
    uint32_t p1[4], p2[4];
#pragma unroll
    for (int e2 = 0; e2 < 4; e2++) {
        float a0 = W1[((size_t)c * E_ + 2 * e2) * KW_ + k];
        float a1 = W1[((size_t)c * E_ + 2 * e2 + 1) * KW_ + k];
        p1[e2] = pack_h2(a0, a1);
        float b0 = W2[((size_t)c * E_ + 2 * e2) * KW_ + k];
        float b1v = W2[((size_t)c * E_ + 2 * e2 + 1) * KW_ + k];
        p2[e2] = pack_h2(b0, b1v);
    }
    *(uint4*)&g_Bh[(size_t)c * KKd + k * E_]        = make_uint4(p1[0], p1[1], p1[2], p1[3]);
    *(uint4*)&g_Bh[(size_t)(C_ + c) * KKd + k * E_] = make_uint4(p2[0], p2[1], p2[2], p2[3]);
}

// ---------------- main fused GEMM + gate + max ----------------
__global__ __launch_bounds__(NTH, 2)
void gemm_gate_max(const float* __restrict__ Z,
                   const float* __restrict__ b1,
                   const float* __restrict__ b2,
                   float* __restrict__ out) {
    extern __shared__ char smem[];
    const uint32_t sb = smem_u32(smem);
    const int tid  = threadIdx.x;
    const int wid  = tid >> 5;
    const int lane = tid & 31;
    const int wm   = wid & 1;        // M group (0..1), 32 rows each
    const int wn   = wid >> 1;       // N group (0..3), 64 cols each
    const int m_base = blockIdx.x * MT;

    const uint32_t fragBase = (uint32_t)((lane % 16) * PITCH + (lane / 16) * 16);
    const uint32_t wmOff = (uint32_t)(wm * 32 * PITCH);
    const uint32_t wnOff = (uint32_t)(wn * 64 * PITCH);

    // ---- A gmem/smem mapping: 2 float4 per thread per chunk ----
    const float* aSrc[2];
    uint32_t     aDst[2];
#pragma unroll
    for (int q = 0; q < 2; q++) {
        int i   = tid + q * 256;       // 0..511
        int row = i >> 3;              // 0..63
        int kw  = (i & 7) * 4;         // float index 0..28
        aSrc[q] = Z + (size_t)(m_base + row) * KKd + kw;
        aDst[q] = (uint32_t)(row * PITCH + kw * 2);
    }
    // ---- B cp.async mapping: 4 granules (16B) per thread ----
    const __half* bSrc[4];
    uint32_t bDst[4];
#pragma unroll
    for (int q = 0; q < 4; q++) {
        int g  = tid + q * 256;        // 0..1023
        int n  = g >> 2;               // 0..255
        int ko = (g & 3) * 8;          // fp16 offset in row
        bSrc[q] = g_Bh + (size_t)n * KKd + ko;
        bDst[q] = (uint32_t)(n * PITCH + ko * 2);
    }

    float acc[2][8][4];
#pragma unroll
    for (int mi = 0; mi < 2; mi++)
#pragma unroll
        for (int ni = 0; ni < 8; ni++)
#pragma unroll
            for (int q = 0; q < 4; q++) acc[mi][ni][q] = 0.0f;

    float4 pA[2];

    // ---- prologue: stages 0,1 fully staged; A regs hold stage 2 ----
#pragma unroll
    for (int s = 0; s < 2; s++) {
#pragma unroll
        for (int q = 0; q < 4; q++)
            cpasync16(sb + SM_B + s * B_STG + bDst[q], bSrc[q] + s * KC);
        cp_commit();
#pragma unroll
        for (int q = 0; q < 2; q++) {
            float4 v = *(const float4*)(aSrc[q] + s * KC);
            sts64(sb + SM_A + s * A_STG + aDst[q], pack_h2(v.x, v.y), pack_h2(v.z, v.w));
        }
    }
#pragma unroll
    for (int q = 0; q < 2; q++) pA[q] = *(const float4*)(aSrc[q] + 2 * KC);

    int cur = 0;   // j % 3
    int wrt = 2;   // (j+2) % 3
    for (int j = 0; j < NCHUNK; ++j) {
        if (j + 2 < NCHUNK) cp_wait1(); else cp_wait0();
        __syncthreads();   // stage j visible; buffer wrt free (readers of j-1 done)

        if (j + 2 < NCHUNK) {
            const int ke = (j + 2) * KC;
#pragma unroll
            for (int q = 0; q < 4; q++)
                cpasync16(sb + SM_B + wrt * B_STG + bDst[q], bSrc[q] + ke);
            cp_commit();
#pragma unroll
            for (int q = 0; q < 2; q++) {
                float4 v = pA[q];
                sts64(sb + SM_A + wrt * A_STG + aDst[q], pack_h2(v.x, v.y), pack_h2(v.z, v.w));
            }
        }
        if (j + 3 < NCHUNK) {
#pragma unroll
            for (int q = 0; q < 2; q++) pA[q] = *(const float4*)(aSrc[q] + (j + 3) * KC);
        }

        // ---- compute chunk j ----
        const uint32_t sA = sb + SM_A + cur * A_STG;
        const uint32_t sB = sb + SM_B + cur * B_STG;
#pragma unroll
        for (int ks = 0; ks < 2; ks++) {
            const uint32_t ko = ks * 32;
            uint32_t af[2][4], bf[4][4];
#pragma unroll
            for (int mi = 0; mi < 2; mi++)
                ldmx4(af[mi], sA + wmOff + mi * (16 * PITCH) + ko + fragBase);
#pragma unroll
            for (int n2 = 0; n2 < 4; n2++)
                ldmx4(bf[n2], sB + wnOff + n2 * (16 * PITCH) + ko + fragBase);
#pragma unroll
            for (int mi = 0; mi < 2; mi++)
#pragma unroll
                for (int ni = 0; ni < 8; ni++)
                    mma16816(acc[mi][ni], af[mi], bf[ni >> 1][(ni & 1)], bf[ni >> 1][(ni & 1) + 2]);
        }

        cur = (cur == STAGES - 1) ? 0 : cur + 1;
        wrt = (wrt == STAGES - 1) ? 0 : wrt + 1;
    }

    // ---- epilogue ----
    __syncthreads();   // pipe done; reuse smem as v2 tile [64][VPITCH] floats

    const int laneR = lane >> 2;
    const int laneC = (lane & 3) * 2;

    if (wn >= 2) {
#pragma unroll
        for (int mi = 0; mi < 2; mi++) {
#pragma unroll
            for (int ni = 0; ni < 8; ni++) {
                int r = wm * 32 + mi * 16 + laneR;
                int c = (wn - 2) * 64 + ni * 8 + laneC;
                uint32_t a0 = sb + (uint32_t)(r * (VPITCH * 4) + c * 4);
                stsf2(a0,                    acc[mi][ni][0], acc[mi][ni][1]);
                stsf2(a0 + 8 * (VPITCH * 4), acc[mi][ni][2], acc[mi][ni][3]);
            }
        }
    }
    __syncthreads();

    if (wn < 2) {
        const float* sV = (const float*)smem;
        const int bidx = blockIdx.x >> 5;   // 32 CTAs per batch
        float gm[8][2];
#pragma unroll
        for (int ni = 0; ni < 8; ni++) {
            const int c = wn * 64 + ni * 8 + laneC;
            const float bb1a = __ldg(&b1[c]),     bb1b = __ldg(&b1[c + 1]);
            const float bb2a = __ldg(&b2[c]),     bb2b = __ldg(&b2[c + 1]);
            float m0 = -INFINITY, m1 = -INFINITY;
#pragma unroll
            for (int mi = 0; mi < 2; mi++) {
                int r0 = wm * 32 + mi * 16 + laneR;
                float v2a0 = sV[r0 * VPITCH + c]           + bb2a;
                float v2b0 = sV[r0 * VPITCH + c + 1]       + bb2b;
                float v2a1 = sV[(r0 + 8) * VPITCH + c]     + bb2a;
                float v2b1 = sV[(r0 + 8) * VPITCH + c + 1] + bb2b;
                float g0 = (acc[mi][ni][0] + bb1a) / (1.0f + __expf(-v2a0));
                float g1 = (acc[mi][ni][1] + bb1b) / (1.0f + __expf(-v2b0));
                float g2 = (acc[mi][ni][2] + bb1a) / (1.0f + __expf(-v2a1));
                float g3 = (acc[mi][ni][3] + bb1b) / (1.0f + __expf(-v2b1));
                m0 = fmaxf(m0, fmaxf(g0, g2));
                m1 = fmaxf(m1, fmaxf(g1, g3));
            }
            gm[ni][0] = m0;
            gm[ni][1] = m1;
        }
#pragma unroll
        for (int ni = 0; ni < 8; ni++) {
#pragma unroll
            for (int off = 4; off < 32; off <<= 1) {
                gm[ni][0] = fmaxf(gm[ni][0], __shfl_xor_sync(0xffffffffu, gm[ni][0], off));
                gm[ni][1] = fmaxf(gm[ni][1], __shfl_xor_sync(0xffffffffu, gm[ni][1], off));
            }
        }
        if (laneR == 0) {
#pragma unroll
            for (int ni = 0; ni < 8; ni++) {
                int c = wn * 64 + ni * 8 + laneC;
                atomicMaxFloat(&out[bidx * C_ + c],     gm[ni][0]);
                atomicMaxFloat(&out[bidx * C_ + c + 1], gm[ni][1]);
            }
        }
    }
}

extern "C" void kernel_launch(void* const* d_in, const int* in_sizes, int n_in,
                              void* d_out, int out_size) {
    const float* z  = (const float*)d_in[0];
    const float* W1 = (const float*)d_in[1];
    const float* b1 = (const float*)d_in[2];
    const float* W2 = (const float*)d_in[3];
    const float* b2 = (const float*)d_in[4];
    float* out = (float*)d_out;
    (void)in_sizes; (void)n_in; (void)out_size;

    cudaFuncSetAttribute(gemm_gate_max, cudaFuncAttributeMaxDynamicSharedMemorySize, SMEMSZ);

    prep_weights<<<(C_ * KW_ + 255) / 256, 256>>>(W1, W2, out);
    gemm_gate_max<<<NCTA, NTH, SMEMSZ>>>(z, b1, b2, out);
}